// round 7
// baseline (speedup 1.0000x reference)
#include <cuda_runtime.h>
#include <cuda_fp16.h>
#include <cstdint>

#define NN 100000
#define EE 3200000
#define DD 16
#define ACT_SLOPE 0.01f
#define ROWW 32              // accumulator row stride (floats): 16 feat + denom @16 + pad

// Scratch (device globals: allocation-free rule). 256B-aligned.
__device__ __align__(256) float  g_featS[NN * DD];     // fp32: accumulated
__device__ __align__(256) __half g_featDh[NN * DD];    // fp16: score-only
__device__ __align__(256) float  g_accumW[NN * ROWW];  // wide rows: feat[0..15], denom[16]

// 256-bit global load (sm_100+).
__device__ __forceinline__ void ldg_v8(const float* __restrict__ p, float* f) {
    asm("ld.global.nc.v8.f32 {%0,%1,%2,%3,%4,%5,%6,%7}, [%8];"
        : "=f"(f[0]), "=f"(f[1]), "=f"(f[2]), "=f"(f[3]),
          "=f"(f[4]), "=f"(f[5]), "=f"(f[6]), "=f"(f[7])
        : "l"(p));
}

__device__ __forceinline__ float4 ldg_v4(const float* __restrict__ p) {
    float4 v;
    asm("ld.global.nc.v4.f32 {%0,%1,%2,%3}, [%4];"
        : "=f"(v.x), "=f"(v.y), "=f"(v.z), "=f"(v.w) : "l"(p));
    return v;
}

__device__ __forceinline__ uint2 ldg_u2(const void* __restrict__ p) {
    uint2 v;
    asm("ld.global.nc.v2.u32 {%0,%1}, [%2];" : "=r"(v.x), "=r"(v.y) : "l"(p));
    return v;
}

// Shared transform core: thread q of a node writes chunk [4q,4q+4) of featS
// (fp32) and featDh (fp16), zeroes accum row slots [4q,4q+4) (+ slots 16..19 by q==0).
__device__ __forceinline__ void transform_store(
    const float* hv, const float* sWs, const float* sWd,
    const float* sbs, const float* sbd, int n, int q)
{
    int c0 = q * 4;
    float fs[4], fd[4];
#pragma unroll
    for (int j = 0; j < 4; j++) { fs[j] = sbs[c0 + j]; fd[j] = sbd[c0 + j]; }
#pragma unroll
    for (int i = 0; i < DD; i++) {
        float hi = hv[i];
#pragma unroll
        for (int j = 0; j < 4; j++) {
            fs[j] = fmaf(hi, sWs[i * DD + c0 + j], fs[j]);
            fd[j] = fmaf(hi, sWd[i * DD + c0 + j], fd[j]);
        }
    }
    reinterpret_cast<float4*>(g_featS + (size_t)n * DD)[q] =
        make_float4(fs[0], fs[1], fs[2], fs[3]);
    __half2 d0 = __floats2half2_rn(fd[0], fd[1]);
    __half2 d1 = __floats2half2_rn(fd[2], fd[3]);
    uint2 st;
    st.x = *reinterpret_cast<unsigned int*>(&d0);
    st.y = *reinterpret_cast<unsigned int*>(&d1);
    *reinterpret_cast<uint2*>(g_featDh + (size_t)n * DD + q * 4) = st;
    // zero accumulator row (red targets: slots 0..19)
    float4* aw = reinterpret_cast<float4*>(g_accumW + (size_t)n * ROWW);
    aw[q] = make_float4(0.f, 0.f, 0.f, 0.f);
    if (q == 0) aw[4] = make_float4(0.f, 0.f, 0.f, 0.f);
}

// ---------------------------------------------------------------------------
// Kernel 1: layer-1 transform from embedding. 4 threads per node.
// ---------------------------------------------------------------------------
__global__ void __launch_bounds__(256) transform1_k(
    const float* __restrict__ h,
    const float* __restrict__ Wsrc, const float* __restrict__ bsrc,
    const float* __restrict__ Wdst, const float* __restrict__ bdst,
    int n_nodes)
{
    __shared__ float sWs[DD * DD], sWd[DD * DD], sbs[DD], sbd[DD];
    int tid = threadIdx.x;
    if (tid < DD * DD) { sWs[tid] = Wsrc[tid]; sWd[tid] = Wdst[tid]; }
    if (tid < DD)      { sbs[tid] = bsrc[tid]; sbd[tid] = bdst[tid]; }
    __syncthreads();

    int g = blockIdx.x * 256 + tid;
    int n = g >> 2, q = g & 3;
    if (n >= n_nodes) return;

    float hv[DD];
    ldg_v8(h + (size_t)n * DD, hv);
    ldg_v8(h + (size_t)n * DD + 8, hv + 8);
    transform_store(hv, sWs, sWd, sbs, sbd, n, q);
}

// ---------------------------------------------------------------------------
// Kernel 2 (fused): layer-1 finalize + layer-2 transform. 4 threads per node.
// h2 = leaky_relu(accum/denom, 0.01) in registers; accum row re-zeroed.
// ---------------------------------------------------------------------------
__global__ void __launch_bounds__(256) transform2_fused_k(
    const float* __restrict__ Wsrc, const float* __restrict__ bsrc,
    const float* __restrict__ Wdst, const float* __restrict__ bdst,
    int n_nodes)
{
    __shared__ float sWs[DD * DD], sWd[DD * DD], sbs[DD], sbd[DD];
    int tid = threadIdx.x;
    if (tid < DD * DD) { sWs[tid] = Wsrc[tid]; sWd[tid] = Wdst[tid]; }
    if (tid < DD)      { sbs[tid] = bsrc[tid]; sbd[tid] = bdst[tid]; }
    __syncthreads();

    int g = blockIdx.x * 256 + tid;
    int n = g >> 2, q = g & 3;
    if (n >= n_nodes) return;

    const float* row = g_accumW + (size_t)n * ROWW;
    float dn = row[DD];
    float inv = (dn > 0.f) ? (1.0f / dn) : 0.0f;

    float hv[DD];
    ldg_v8(row, hv);
    ldg_v8(row + 8, hv + 8);
#pragma unroll
    for (int k = 0; k < DD; k++) {
        float r = hv[k] * inv;
        hv[k] = (r > 0.f) ? r : ACT_SLOPE * r;
    }
    transform_store(hv, sWs, sWd, sbs, sbd, n, q);
}

// ---------------------------------------------------------------------------
// Kernel 3: edge pass, 5 lanes per edge (6 edges/warp, lanes 30-31 idle).
// Lanes p<4: gather featS fp32 / featD fp16 chunk p, score partial.
// Score reduced over the 4 compute lanes (2x shfl_down, arms stay in-group),
// exp broadcast to all 5 lanes. ONE red.v4 warp instruction accumulates all
// 17 values: lanes p<4 add ex*fa at row offset 16*p; lane p==4 adds
// {ex,0,0,0} at offset 64 (denom slot) -- same 128B line, same instruction.
// ~3 L1tex wavefronts/edge (featS + featD + red).
// score = 0.6*dot(a,x) + 0.4*dot(a,|x|)  (== dot(a, lrelu(x,0.2)))
// No segment-max (softmax shift invariance; scores ~N(0,1)).
// ---------------------------------------------------------------------------
__global__ void __launch_bounds__(256) edge_kernel_coop5(
    const int* __restrict__ src, const int* __restrict__ dst,
    const float* __restrict__ attn, int n_edges)
{
    __shared__ float sa[DD];
    if (threadIdx.x < DD) sa[threadIdx.x] = attn[threadIdx.x];
    __syncthreads();

    int lane = threadIdx.x & 31;
    int grp  = lane / 5;            // edge slot in warp: 0..5 (6 = idle)
    int p    = lane - grp * 5;      // 0..4 within group
    int warp_global = (blockIdx.x * 256 + threadIdx.x) >> 5;

    int e = warp_global * 6 + grp;
    bool valid = (grp < 6) && (e < n_edges);
    int ec = valid ? e : 0;

    int s = __ldg(&src[ec]);
    int t = __ldg(&dst[ec]);

    float part = 0.f;
    float4 fa = make_float4(0.f, 0.f, 0.f, 0.f);
    if (p < 4) {
        fa = ldg_v4(g_featS + (size_t)s * DD + p * 4);
        uint2 hb = ldg_u2(g_featDh + (size_t)t * DD + p * 4);
        float2 b01 = __half22float2(*reinterpret_cast<__half2*>(&hb.x));
        float2 b23 = __half22float2(*reinterpret_cast<__half2*>(&hb.y));

        float a0 = sa[p * 4 + 0], a1 = sa[p * 4 + 1];
        float a2 = sa[p * 4 + 2], a3 = sa[p * 4 + 3];

        float x0 = fa.x + b01.x, x1 = fa.y + b01.y;
        float x2 = fa.z + b23.x, x3 = fa.w + b23.y;
        float lin = a0 * x0;
        lin = fmaf(a1, x1, lin);
        lin = fmaf(a2, x2, lin);
        lin = fmaf(a3, x3, lin);
        float ab = a0 * fabsf(x0);
        ab = fmaf(a1, fabsf(x1), ab);
        ab = fmaf(a2, fabsf(x2), ab);
        ab = fmaf(a3, fabsf(x3), ab);
        part = fmaf(0.6f, lin, 0.4f * ab);
    }

    // group reduce: s2 at base lane = p0+p1+p2+p3 (arms stay within the group)
    float s1 = part + __shfl_down_sync(0xffffffffu, part, 1);
    float s2 = s1 + __shfl_down_sync(0xffffffffu, s1, 2);
    float ex = __expf(s2);
    // broadcast base lane's ex to the whole 5-lane group
    ex = __shfl_sync(0xffffffffu, ex, lane - p);

    if (valid) {
        float v0, v1, v2, v3;
        int off;
        if (p < 4) {
            v0 = ex * fa.x; v1 = ex * fa.y; v2 = ex * fa.z; v3 = ex * fa.w;
            off = p * 4;
        } else {
            v0 = ex; v1 = 0.f; v2 = 0.f; v3 = 0.f;
            off = DD;  // denom slot at row offset 64B
        }
        float* ap = g_accumW + (size_t)t * ROWW + off;
        asm volatile("red.global.add.v4.f32 [%0], {%1, %2, %3, %4};"
                     :: "l"(ap), "f"(v0), "f"(v1), "f"(v2), "f"(v3)
                     : "memory");
    }
}

// ---------------------------------------------------------------------------
// Kernel 4: layer-2 finalize -> d_out.
// ---------------------------------------------------------------------------
__global__ void __launch_bounds__(256) finalize2_k(float* __restrict__ out, int n_nodes)
{
    int n = blockIdx.x * blockDim.x + threadIdx.x;
    if (n >= n_nodes) return;

    const float* row = g_accumW + (size_t)n * ROWW;
    float dn = row[DD];
    float inv = (dn > 0.f) ? (1.0f / dn) : 0.0f;

    const float4* ap = reinterpret_cast<const float4*>(row);
    float4* op = reinterpret_cast<float4*>(out + (size_t)n * DD);
#pragma unroll
    for (int q = 0; q < 4; q++) {
        float4 v = ap[q];
        float r0 = v.x * inv, r1 = v.y * inv, r2 = v.z * inv, r3 = v.w * inv;
        r0 = (r0 > 0.f) ? r0 : ACT_SLOPE * r0;
        r1 = (r1 > 0.f) ? r1 : ACT_SLOPE * r1;
        r2 = (r2 > 0.f) ? r2 : ACT_SLOPE * r2;
        r3 = (r3 > 0.f) ? r3 : ACT_SLOPE * r3;
        op[q] = make_float4(r0, r1, r2, r3);
    }
}

// ---------------------------------------------------------------------------
extern "C" void kernel_launch(void* const* d_in, const int* in_sizes, int n_in,
                              void* d_out, int out_size)
{
    const float* emb   = (const float*)d_in[0];
    const int*   src1  = (const int*)d_in[1];
    const int*   dst1  = (const int*)d_in[2];
    const int*   src2  = (const int*)d_in[3];
    const int*   dst2  = (const int*)d_in[4];
    const float* Wsrc1 = (const float*)d_in[5];
    const float* bsrc1 = (const float*)d_in[6];
    const float* Wdst1 = (const float*)d_in[7];
    const float* bdst1 = (const float*)d_in[8];
    const float* attn1 = (const float*)d_in[9];
    const float* Wsrc2 = (const float*)d_in[10];
    const float* bsrc2 = (const float*)d_in[11];
    const float* Wdst2 = (const float*)d_in[12];
    const float* bdst2 = (const float*)d_in[13];
    const float* attn2 = (const float*)d_in[14];

    int n_nodes  = in_sizes[0] / DD;
    int n_edges1 = in_sizes[1];
    int n_edges2 = in_sizes[3];
    float* out = (float*)d_out;

    int nblk4 = (n_nodes * 4 + 255) / 256;
    int nblk  = (n_nodes + 255) / 256;
    // 6 edges per warp, 8 warps per block -> 48 edges/block
    int eblk1 = (n_edges1 + 47) / 48;
    int eblk2 = (n_edges2 + 47) / 48;

    transform1_k<<<nblk4, 256>>>(emb, Wsrc1, bsrc1, Wdst1, bdst1, n_nodes);
    edge_kernel_coop5<<<eblk1, 256>>>(src1, dst1, attn1, n_edges1);
    transform2_fused_k<<<nblk4, 256>>>(Wsrc2, bsrc2, Wdst2, bdst2, n_nodes);
    edge_kernel_coop5<<<eblk2, 256>>>(src2, dst2, attn2, n_edges2);
    finalize2_k<<<nblk, 256>>>(out, n_nodes);
}

// round 9
// speedup vs baseline: 1.1939x; 1.1939x over previous
#include <cuda_runtime.h>
#include <cuda_fp16.h>
#include <cstdint>

#define NN 100000
#define EE 3200000
#define DD 16
#define ACT_SLOPE 0.01f

// Scratch (device globals: allocation-free rule). 256B-aligned.
__device__ __align__(256) float  g_featS[NN * DD];    // fp32: gathered + products
__device__ __align__(256) __half g_featDh[NN * DD];   // fp16: score-only
// Accumulator rows: 64B each = 16 fp16 numerator halves (32B) + fp32 denom @32B + pad.
__device__ __align__(256) __half g_accRow[NN * 32];

// 256-bit global load (sm_100+).
__device__ __forceinline__ void ldg_v8(const float* __restrict__ p, float* f) {
    asm("ld.global.nc.v8.f32 {%0,%1,%2,%3,%4,%5,%6,%7}, [%8];"
        : "=f"(f[0]), "=f"(f[1]), "=f"(f[2]), "=f"(f[3]),
          "=f"(f[4]), "=f"(f[5]), "=f"(f[6]), "=f"(f[7])
        : "l"(p));
}

__device__ __forceinline__ float4 ldg_v4(const float* __restrict__ p) {
    float4 v;
    asm("ld.global.nc.v4.f32 {%0,%1,%2,%3}, [%4];"
        : "=f"(v.x), "=f"(v.y), "=f"(v.z), "=f"(v.w) : "l"(p));
    return v;
}

__device__ __forceinline__ uint2 ldg_u2(const void* __restrict__ p) {
    uint2 v;
    asm("ld.global.nc.v2.u32 {%0,%1}, [%2];" : "=r"(v.x), "=r"(v.y) : "l"(p));
    return v;
}

// Read an accumulator row: 16 halves -> hv[16] floats, plus denom.
__device__ __forceinline__ float read_acc_row(int n, float* hv) {
    const __half* row = g_accRow + (size_t)n * 32;
    uint4 ra = *reinterpret_cast<const uint4*>(row);      // halves 0..7
    uint4 rb = *reinterpret_cast<const uint4*>(row + 8);  // halves 8..15
    const unsigned int u[8] = {ra.x, ra.y, ra.z, ra.w, rb.x, rb.y, rb.z, rb.w};
#pragma unroll
    for (int i = 0; i < 8; i++) {
        float2 f = __half22float2(*reinterpret_cast<const __half2*>(&u[i]));
        hv[2 * i] = f.x;
        hv[2 * i + 1] = f.y;
    }
    return *reinterpret_cast<const float*>(row + 16);     // denom @ byte 32
}

// Shared transform core: thread q of a node writes chunk [4q,4q+4) of featS
// (fp32) and featDh (fp16), zeroes its 16B slice of the accumulator row.
__device__ __forceinline__ void transform_store(
    const float* hv, const float* sWs, const float* sWd,
    const float* sbs, const float* sbd, int n, int q)
{
    int c0 = q * 4;
    float fs[4], fd[4];
#pragma unroll
    for (int j = 0; j < 4; j++) { fs[j] = sbs[c0 + j]; fd[j] = sbd[c0 + j]; }
#pragma unroll
    for (int i = 0; i < DD; i++) {
        float hi = hv[i];
#pragma unroll
        for (int j = 0; j < 4; j++) {
            fs[j] = fmaf(hi, sWs[i * DD + c0 + j], fs[j]);
            fd[j] = fmaf(hi, sWd[i * DD + c0 + j], fd[j]);
        }
    }
    reinterpret_cast<float4*>(g_featS + (size_t)n * DD)[q] =
        make_float4(fs[0], fs[1], fs[2], fs[3]);
    __half2 d0 = __floats2half2_rn(fd[0], fd[1]);
    __half2 d1 = __floats2half2_rn(fd[2], fd[3]);
    uint2 st;
    st.x = *reinterpret_cast<unsigned int*>(&d0);
    st.y = *reinterpret_cast<unsigned int*>(&d1);
    *reinterpret_cast<uint2*>(g_featDh + (size_t)n * DD + q * 4) = st;
    // zero 16B of the 64B accumulator row (4 threads cover it, incl. denom+pad)
    reinterpret_cast<uint4*>(g_accRow + (size_t)n * 32)[q] =
        make_uint4(0u, 0u, 0u, 0u);
}

// ---------------------------------------------------------------------------
// Kernel 1: layer-1 transform from embedding. 4 threads per node.
// ---------------------------------------------------------------------------
__global__ void __launch_bounds__(256) transform1_k(
    const float* __restrict__ h,
    const float* __restrict__ Wsrc, const float* __restrict__ bsrc,
    const float* __restrict__ Wdst, const float* __restrict__ bdst,
    int n_nodes)
{
    __shared__ float sWs[DD * DD], sWd[DD * DD], sbs[DD], sbd[DD];
    int tid = threadIdx.x;
    if (tid < DD * DD) { sWs[tid] = Wsrc[tid]; sWd[tid] = Wdst[tid]; }
    if (tid < DD)      { sbs[tid] = bsrc[tid]; sbd[tid] = bdst[tid]; }
    __syncthreads();

    int g = blockIdx.x * 256 + tid;
    int n = g >> 2, q = g & 3;
    if (n >= n_nodes) return;

    float hv[DD];
    ldg_v8(h + (size_t)n * DD, hv);
    ldg_v8(h + (size_t)n * DD + 8, hv + 8);
    transform_store(hv, sWs, sWd, sbs, sbd, n, q);
}

// ---------------------------------------------------------------------------
// Kernel 2 (fused): layer-1 finalize + layer-2 transform. 4 threads per node.
// h2 = leaky_relu(accum/denom, 0.01) in registers; accum row re-zeroed.
// ---------------------------------------------------------------------------
__global__ void __launch_bounds__(256) transform2_fused_k(
    const float* __restrict__ Wsrc, const float* __restrict__ bsrc,
    const float* __restrict__ Wdst, const float* __restrict__ bdst,
    int n_nodes)
{
    __shared__ float sWs[DD * DD], sWd[DD * DD], sbs[DD], sbd[DD];
    int tid = threadIdx.x;
    if (tid < DD * DD) { sWs[tid] = Wsrc[tid]; sWd[tid] = Wdst[tid]; }
    if (tid < DD)      { sbs[tid] = bsrc[tid]; sbd[tid] = bdst[tid]; }
    __syncthreads();

    int g = blockIdx.x * 256 + tid;
    int n = g >> 2, q = g & 3;
    if (n >= n_nodes) return;

    float hv[DD];
    float dn = read_acc_row(n, hv);
    float inv = (dn > 0.f) ? (1.0f / dn) : 0.0f;
#pragma unroll
    for (int k = 0; k < DD; k++) {
        float r = hv[k] * inv;
        hv[k] = (r > 0.f) ? r : ACT_SLOPE * r;
    }
    transform_store(hv, sWs, sWd, sbs, sbd, n, q);
}

// ---------------------------------------------------------------------------
// Kernel 3: edge pass, 4 lanes per edge (8 edges/warp).
// Lane p: gather featS fp32 / featD fp16 chunk [4p,4p+4), score partial,
// xor-reduce over the 4-lane group (every lane gets the full score).
// Numerator accumulated in fp16: each lane packs its 4 products into 2x f16x2;
// lanes 0,2 pull their neighbor's pair via shfl_xor(1) and issue ONE
// red.global.add.noftz.v4.f16x2 (16B) each; lane 1 does the fp32 denom red.
// Red lanes/edge: 3 (was 5) -> REDG lane-throughput floor drops 40%.
// score = 0.6*dot(a,x) + 0.4*dot(a,|x|)  (== dot(a, lrelu(x,0.2)))
// No segment-max (softmax shift invariance; scores ~N(0,1)).
// ---------------------------------------------------------------------------
__global__ void __launch_bounds__(256) edge_kernel_h16(
    const int* __restrict__ src, const int* __restrict__ dst,
    const float* __restrict__ attn, int n_edges)
{
    __shared__ float sa[DD];
    if (threadIdx.x < DD) sa[threadIdx.x] = attn[threadIdx.x];
    __syncthreads();

    int lane = threadIdx.x & 31;
    int p = lane & 3;
    int sub = lane >> 2;
    int warp_global = (blockIdx.x * 256 + threadIdx.x) >> 5;

    float a0 = sa[p * 4 + 0], a1 = sa[p * 4 + 1];
    float a2 = sa[p * 4 + 2], a3 = sa[p * 4 + 3];

    int e = warp_global * 8 + sub;
    bool valid = (e < n_edges);
    int ec = valid ? e : 0;

    int s = __ldg(&src[ec]);
    int t = __ldg(&dst[ec]);

    float4 fa = ldg_v4(g_featS + (size_t)s * DD + p * 4);
    uint2 hb = ldg_u2(g_featDh + (size_t)t * DD + p * 4);
    float2 b01 = __half22float2(*reinterpret_cast<__half2*>(&hb.x));
    float2 b23 = __half22float2(*reinterpret_cast<__half2*>(&hb.y));

    float x0 = fa.x + b01.x, x1 = fa.y + b01.y;
    float x2 = fa.z + b23.x, x3 = fa.w + b23.y;
    float lin = a0 * x0;
    lin = fmaf(a1, x1, lin);
    lin = fmaf(a2, x2, lin);
    lin = fmaf(a3, x3, lin);
    float ab = a0 * fabsf(x0);
    ab = fmaf(a1, fabsf(x1), ab);
    ab = fmaf(a2, fabsf(x2), ab);
    ab = fmaf(a3, fabsf(x3), ab);
    float part = fmaf(0.6f, lin, 0.4f * ab);

    // xor-reduce across 4-lane group: every lane ends with the full score
    part += __shfl_xor_sync(0xffffffffu, part, 1);
    part += __shfl_xor_sync(0xffffffffu, part, 2);

    float ex = __expf(part);

    // pack this lane's 4 products as fp16x2 pair
    __half2 p0 = __floats2half2_rn(ex * fa.x, ex * fa.y);
    __half2 p1 = __floats2half2_rn(ex * fa.z, ex * fa.w);
    unsigned int u0 = *reinterpret_cast<unsigned int*>(&p0);
    unsigned int u1 = *reinterpret_cast<unsigned int*>(&p1);
    // even lanes take their odd neighbor's pair
    unsigned int o0 = __shfl_xor_sync(0xffffffffu, u0, 1);
    unsigned int o1 = __shfl_xor_sync(0xffffffffu, u1, 1);

    if (valid) {
        char* row = reinterpret_cast<char*>(g_accRow) + (size_t)t * 64;
        if ((p & 1) == 0) {
            // lane 0 -> halves [0..8) at +0; lane 2 -> halves [8..16) at +16
            asm volatile("red.global.add.noftz.v4.f16x2 [%0], {%1, %2, %3, %4};"
                         :: "l"(row + (p >> 1) * 16),
                            "r"(u0), "r"(u1), "r"(o0), "r"(o1)
                         : "memory");
        } else if (p == 1) {
            asm volatile("red.global.add.f32 [%0], %1;"
                         :: "l"(row + 32), "f"(ex) : "memory");
        }
    }
}

// ---------------------------------------------------------------------------
// Kernel 4: layer-2 finalize -> d_out.
// ---------------------------------------------------------------------------
__global__ void __launch_bounds__(256) finalize2_k(float* __restrict__ out, int n_nodes)
{
    int n = blockIdx.x * blockDim.x + threadIdx.x;
    if (n >= n_nodes) return;

    float hv[DD];
    float dn = read_acc_row(n, hv);
    float inv = (dn > 0.f) ? (1.0f / dn) : 0.0f;

    float4* op = reinterpret_cast<float4*>(out + (size_t)n * DD);
#pragma unroll
    for (int q = 0; q < 4; q++) {
        float r0 = hv[4*q + 0] * inv;
        float r1 = hv[4*q + 1] * inv;
        float r2 = hv[4*q + 2] * inv;
        float r3 = hv[4*q + 3] * inv;
        r0 = (r0 > 0.f) ? r0 : ACT_SLOPE * r0;
        r1 = (r1 > 0.f) ? r1 : ACT_SLOPE * r1;
        r2 = (r2 > 0.f) ? r2 : ACT_SLOPE * r2;
        r3 = (r3 > 0.f) ? r3 : ACT_SLOPE * r3;
        op[q] = make_float4(r0, r1, r2, r3);
    }
}

// ---------------------------------------------------------------------------
extern "C" void kernel_launch(void* const* d_in, const int* in_sizes, int n_in,
                              void* d_out, int out_size)
{
    const float* emb   = (const float*)d_in[0];
    const int*   src1  = (const int*)d_in[1];
    const int*   dst1  = (const int*)d_in[2];
    const int*   src2  = (const int*)d_in[3];
    const int*   dst2  = (const int*)d_in[4];
    const float* Wsrc1 = (const float*)d_in[5];
    const float* bsrc1 = (const float*)d_in[6];
    const float* Wdst1 = (const float*)d_in[7];
    const float* bdst1 = (const float*)d_in[8];
    const float* attn1 = (const float*)d_in[9];
    const float* Wsrc2 = (const float*)d_in[10];
    const float* bsrc2 = (const float*)d_in[11];
    const float* Wdst2 = (const float*)d_in[12];
    const float* bdst2 = (const float*)d_in[13];
    const float* attn2 = (const float*)d_in[14];

    int n_nodes  = in_sizes[0] / DD;
    int n_edges1 = in_sizes[1];
    int n_edges2 = in_sizes[3];
    float* out = (float*)d_out;

    int nblk4 = (n_nodes * 4 + 255) / 256;
    int nblk  = (n_nodes + 255) / 256;
    int eblk1 = (n_edges1 + 63) / 64;   // 64 edges per 256-thread block
    int eblk2 = (n_edges2 + 63) / 64;

    transform1_k<<<nblk4, 256>>>(emb, Wsrc1, bsrc1, Wdst1, bdst1, n_nodes);
    edge_kernel_h16<<<eblk1, 256>>>(src1, dst1, attn1, n_edges1);
    transform2_fused_k<<<nblk4, 256>>>(Wsrc2, bsrc2, Wdst2, bdst2, n_nodes);
    edge_kernel_h16<<<eblk2, 256>>>(src2, dst2, attn2, n_edges2);
    finalize2_k<<<nblk, 256>>>(out, n_nodes);
}

// round 13
// speedup vs baseline: 1.2638x; 1.0586x over previous
#include <cuda_runtime.h>
#include <cuda_fp16.h>
#include <cstdint>

#define NN 100000
#define EE 3200000
#define DD 16
#define ACT_SLOPE 0.01f

// Scratch (device globals: allocation-free rule). 256B-aligned.
__device__ __align__(256) float  g_featS[NN * DD];    // fp32: gathered + products
__device__ __align__(256) __half g_featDh[NN * DD];   // fp16: score-only
// Accumulator rows: 64B each = 16 fp16 numerator halves (32B) + fp32 denom @32B + pad.
__device__ __align__(256) __half g_accRow[NN * 32];

// 256-bit global load (sm_100+).
__device__ __forceinline__ void ldg_v8(const float* __restrict__ p, float* f) {
    asm("ld.global.nc.v8.f32 {%0,%1,%2,%3,%4,%5,%6,%7}, [%8];"
        : "=f"(f[0]), "=f"(f[1]), "=f"(f[2]), "=f"(f[3]),
          "=f"(f[4]), "=f"(f[5]), "=f"(f[6]), "=f"(f[7])
        : "l"(p));
}

__device__ __forceinline__ float4 ldg_v4(const float* __restrict__ p) {
    float4 v;
    asm("ld.global.nc.v4.f32 {%0,%1,%2,%3}, [%4];"
        : "=f"(v.x), "=f"(v.y), "=f"(v.z), "=f"(v.w) : "l"(p));
    return v;
}

__device__ __forceinline__ uint2 ldg_u2(const void* __restrict__ p) {
    uint2 v;
    asm("ld.global.nc.v2.u32 {%0,%1}, [%2];" : "=r"(v.x), "=r"(v.y) : "l"(p));
    return v;
}

// Read an accumulator row: 16 halves -> hv[16] floats, plus denom.
__device__ __forceinline__ float read_acc_row(int n, float* hv) {
    const __half* row = g_accRow + (size_t)n * 32;
    uint4 ra = *reinterpret_cast<const uint4*>(row);      // halves 0..7
    uint4 rb = *reinterpret_cast<const uint4*>(row + 8);  // halves 8..15
    const unsigned int u[8] = {ra.x, ra.y, ra.z, ra.w, rb.x, rb.y, rb.z, rb.w};
#pragma unroll
    for (int i = 0; i < 8; i++) {
        float2 f = __half22float2(*reinterpret_cast<const __half2*>(&u[i]));
        hv[2 * i] = f.x;
        hv[2 * i + 1] = f.y;
    }
    return *reinterpret_cast<const float*>(row + 16);     // denom @ byte 32
}

// Shared transform core: thread q of a node writes chunk [4q,4q+4) of featS
// (fp32) and featDh (fp16), zeroes its 16B slice of the accumulator row.
__device__ __forceinline__ void transform_store(
    const float* hv, const float* sWs, const float* sWd,
    const float* sbs, const float* sbd, int n, int q)
{
    int c0 = q * 4;
    float fs[4], fd[4];
#pragma unroll
    for (int j = 0; j < 4; j++) { fs[j] = sbs[c0 + j]; fd[j] = sbd[c0 + j]; }
#pragma unroll
    for (int i = 0; i < DD; i++) {
        float hi = hv[i];
#pragma unroll
        for (int j = 0; j < 4; j++) {
            fs[j] = fmaf(hi, sWs[i * DD + c0 + j], fs[j]);
            fd[j] = fmaf(hi, sWd[i * DD + c0 + j], fd[j]);
        }
    }
    reinterpret_cast<float4*>(g_featS + (size_t)n * DD)[q] =
        make_float4(fs[0], fs[1], fs[2], fs[3]);
    __half2 d0 = __floats2half2_rn(fd[0], fd[1]);
    __half2 d1 = __floats2half2_rn(fd[2], fd[3]);
    uint2 st;
    st.x = *reinterpret_cast<unsigned int*>(&d0);
    st.y = *reinterpret_cast<unsigned int*>(&d1);
    *reinterpret_cast<uint2*>(g_featDh + (size_t)n * DD + q * 4) = st;
    // zero 16B of the 64B accumulator row (4 threads cover it, incl. denom+pad)
    reinterpret_cast<uint4*>(g_accRow + (size_t)n * 32)[q] =
        make_uint4(0u, 0u, 0u, 0u);
}

// ---------------------------------------------------------------------------
// Kernel 1: layer-1 transform from embedding. 4 threads per node.
// ---------------------------------------------------------------------------
__global__ void __launch_bounds__(256) transform1_k(
    const float* __restrict__ h,
    const float* __restrict__ Wsrc, const float* __restrict__ bsrc,
    const float* __restrict__ Wdst, const float* __restrict__ bdst,
    int n_nodes)
{
    __shared__ float sWs[DD * DD], sWd[DD * DD], sbs[DD], sbd[DD];
    int tid = threadIdx.x;
    if (tid < DD * DD) { sWs[tid] = Wsrc[tid]; sWd[tid] = Wdst[tid]; }
    if (tid < DD)      { sbs[tid] = bsrc[tid]; sbd[tid] = bdst[tid]; }
    __syncthreads();

    int g = blockIdx.x * 256 + tid;
    int n = g >> 2, q = g & 3;
    if (n >= n_nodes) return;

    float hv[DD];
    ldg_v8(h + (size_t)n * DD, hv);
    ldg_v8(h + (size_t)n * DD + 8, hv + 8);
    transform_store(hv, sWs, sWd, sbs, sbd, n, q);
}

// ---------------------------------------------------------------------------
// Kernel 2 (fused): layer-1 finalize + layer-2 transform. 4 threads per node.
// ---------------------------------------------------------------------------
__global__ void __launch_bounds__(256) transform2_fused_k(
    const float* __restrict__ Wsrc, const float* __restrict__ bsrc,
    const float* __restrict__ Wdst, const float* __restrict__ bdst,
    int n_nodes)
{
    __shared__ float sWs[DD * DD], sWd[DD * DD], sbs[DD], sbd[DD];
    int tid = threadIdx.x;
    if (tid < DD * DD) { sWs[tid] = Wsrc[tid]; sWd[tid] = Wdst[tid]; }
    if (tid < DD)      { sbs[tid] = bsrc[tid]; sbd[tid] = bdst[tid]; }
    __syncthreads();

    int g = blockIdx.x * 256 + tid;
    int n = g >> 2, q = g & 3;
    if (n >= n_nodes) return;

    float hv[DD];
    float dn = read_acc_row(n, hv);
    float inv = (dn > 0.f) ? (1.0f / dn) : 0.0f;
#pragma unroll
    for (int k = 0; k < DD; k++) {
        float r = hv[k] * inv;
        hv[k] = (r > 0.f) ? r : ACT_SLOPE * r;
    }
    transform_store(hv, sWs, sWd, sbs, sbd, n, q);
}

// ---------------------------------------------------------------------------
// Kernel 3: edge pass, 4 lanes per edge, TWO edges per thread (16 edges/warp).
// The two edge pipelines interleave for doubled memory-level parallelism.
// Lane p handles chunk [4p,4p+4) of both its edges.
// Numerator accumulated in fp16 (lanes 0,2: one red.v4.f16x2 each);
// lane 1: fp32 denom red. 3 red lanes/edge.
// score = 0.6*dot(a,x) + 0.4*dot(a,|x|)  (== dot(a, lrelu(x,0.2)))
// No segment-max (softmax shift invariance; scores ~N(0,1)).
// ---------------------------------------------------------------------------
__global__ void __launch_bounds__(256) edge_kernel_h16x2(
    const int* __restrict__ src, const int* __restrict__ dst,
    const float* __restrict__ attn, int n_edges)
{
    __shared__ float sa[DD];
    if (threadIdx.x < DD) sa[threadIdx.x] = attn[threadIdx.x];
    __syncthreads();

    int lane = threadIdx.x & 31;
    int p = lane & 3;
    int sub = lane >> 2;
    int warp_global = (blockIdx.x * 256 + threadIdx.x) >> 5;

    float a0 = sa[p * 4 + 0], a1 = sa[p * 4 + 1];
    float a2 = sa[p * 4 + 2], a3 = sa[p * 4 + 3];

    int e0 = warp_global * 16 + sub;
    int e1 = e0 + 8;
    bool valid0 = (e0 < n_edges);
    bool valid1 = (e1 < n_edges);
    int ec0 = valid0 ? e0 : 0;
    int ec1 = valid1 ? e1 : 0;

    // issue all index loads up front
    int s0 = __ldg(&src[ec0]);
    int s1 = __ldg(&src[ec1]);
    int t0 = __ldg(&dst[ec0]);
    int t1 = __ldg(&dst[ec1]);

    // issue all 4 gathers before consuming any
    float4 fa0 = ldg_v4(g_featS + (size_t)s0 * DD + p * 4);
    float4 fa1 = ldg_v4(g_featS + (size_t)s1 * DD + p * 4);
    uint2 hb0 = ldg_u2(g_featDh + (size_t)t0 * DD + p * 4);
    uint2 hb1 = ldg_u2(g_featDh + (size_t)t1 * DD + p * 4);

    // ---- edge 0 score partial ----
    float2 b01 = __half22float2(*reinterpret_cast<__half2*>(&hb0.x));
    float2 b23 = __half22float2(*reinterpret_cast<__half2*>(&hb0.y));
    float x0 = fa0.x + b01.x, x1 = fa0.y + b01.y;
    float x2 = fa0.z + b23.x, x3 = fa0.w + b23.y;
    float lin0 = a0 * x0;
    lin0 = fmaf(a1, x1, lin0);
    lin0 = fmaf(a2, x2, lin0);
    lin0 = fmaf(a3, x3, lin0);
    float ab0 = a0 * fabsf(x0);
    ab0 = fmaf(a1, fabsf(x1), ab0);
    ab0 = fmaf(a2, fabsf(x2), ab0);
    ab0 = fmaf(a3, fabsf(x3), ab0);
    float part0 = fmaf(0.6f, lin0, 0.4f * ab0);

    // ---- edge 1 score partial ----
    float2 c01 = __half22float2(*reinterpret_cast<__half2*>(&hb1.x));
    float2 c23 = __half22float2(*reinterpret_cast<__half2*>(&hb1.y));
    float y0 = fa1.x + c01.x, y1 = fa1.y + c01.y;
    float y2 = fa1.z + c23.x, y3 = fa1.w + c23.y;
    float lin1 = a0 * y0;
    lin1 = fmaf(a1, y1, lin1);
    lin1 = fmaf(a2, y2, lin1);
    lin1 = fmaf(a3, y3, lin1);
    float ab1 = a0 * fabsf(y0);
    ab1 = fmaf(a1, fabsf(y1), ab1);
    ab1 = fmaf(a2, fabsf(y2), ab1);
    ab1 = fmaf(a3, fabsf(y3), ab1);
    float part1 = fmaf(0.6f, lin1, 0.4f * ab1);

    // xor-reduce across 4-lane group, both edges interleaved
    part0 += __shfl_xor_sync(0xffffffffu, part0, 1);
    part1 += __shfl_xor_sync(0xffffffffu, part1, 1);
    part0 += __shfl_xor_sync(0xffffffffu, part0, 2);
    part1 += __shfl_xor_sync(0xffffffffu, part1, 2);

    float ex0 = __expf(part0);
    float ex1 = __expf(part1);

    // pack products, exchange neighbor pairs
    __half2 q00 = __floats2half2_rn(ex0 * fa0.x, ex0 * fa0.y);
    __half2 q01 = __floats2half2_rn(ex0 * fa0.z, ex0 * fa0.w);
    __half2 q10 = __floats2half2_rn(ex1 * fa1.x, ex1 * fa1.y);
    __half2 q11 = __floats2half2_rn(ex1 * fa1.z, ex1 * fa1.w);
    unsigned int u00 = *reinterpret_cast<unsigned int*>(&q00);
    unsigned int u01 = *reinterpret_cast<unsigned int*>(&q01);
    unsigned int u10 = *reinterpret_cast<unsigned int*>(&q10);
    unsigned int u11 = *reinterpret_cast<unsigned int*>(&q11);
    unsigned int o00 = __shfl_xor_sync(0xffffffffu, u00, 1);
    unsigned int o01 = __shfl_xor_sync(0xffffffffu, u01, 1);
    unsigned int o10 = __shfl_xor_sync(0xffffffffu, u10, 1);
    unsigned int o11 = __shfl_xor_sync(0xffffffffu, u11, 1);

    if (valid0) {
        char* row = reinterpret_cast<char*>(g_accRow) + (size_t)t0 * 64;
        if ((p & 1) == 0) {
            asm volatile("red.global.add.noftz.v4.f16x2 [%0], {%1, %2, %3, %4};"
                         :: "l"(row + (p >> 1) * 16),
                            "r"(u00), "r"(u01), "r"(o00), "r"(o01)
                         : "memory");
        } else if (p == 1) {
            asm volatile("red.global.add.f32 [%0], %1;"
                         :: "l"(row + 32), "f"(ex0) : "memory");
        }
    }
    if (valid1) {
        char* row = reinterpret_cast<char*>(g_accRow) + (size_t)t1 * 64;
        if ((p & 1) == 0) {
            asm volatile("red.global.add.noftz.v4.f16x2 [%0], {%1, %2, %3, %4};"
                         :: "l"(row + (p >> 1) * 16),
                            "r"(u10), "r"(u11), "r"(o10), "r"(o11)
                         : "memory");
        } else if (p == 1) {
            asm volatile("red.global.add.f32 [%0], %1;"
                         :: "l"(row + 32), "f"(ex1) : "memory");
        }
    }
}

// ---------------------------------------------------------------------------
// Kernel 4: layer-2 finalize -> d_out.
// ---------------------------------------------------------------------------
__global__ void __launch_bounds__(256) finalize2_k(float* __restrict__ out, int n_nodes)
{
    int n = blockIdx.x * blockDim.x + threadIdx.x;
    if (n >= n_nodes) return;

    float hv[DD];
    float dn = read_acc_row(n, hv);
    float inv = (dn > 0.f) ? (1.0f / dn) : 0.0f;

    float4* op = reinterpret_cast<float4*>(out + (size_t)n * DD);
#pragma unroll
    for (int q = 0; q < 4; q++) {
        float r0 = hv[4*q + 0] * inv;
        float r1 = hv[4*q + 1] * inv;
        float r2 = hv[4*q + 2] * inv;
        float r3 = hv[4*q + 3] * inv;
        r0 = (r0 > 0.f) ? r0 : ACT_SLOPE * r0;
        r1 = (r1 > 0.f) ? r1 : ACT_SLOPE * r1;
        r2 = (r2 > 0.f) ? r2 : ACT_SLOPE * r2;
        r3 = (r3 > 0.f) ? r3 : ACT_SLOPE * r3;
        op[q] = make_float4(r0, r1, r2, r3);
    }
}

// ---------------------------------------------------------------------------
extern "C" void kernel_launch(void* const* d_in, const int* in_sizes, int n_in,
                              void* d_out, int out_size)
{
    const float* emb   = (const float*)d_in[0];
    const int*   src1  = (const int*)d_in[1];
    const int*   dst1  = (const int*)d_in[2];
    const int*   src2  = (const int*)d_in[3];
    const int*   dst2  = (const int*)d_in[4];
    const float* Wsrc1 = (const float*)d_in[5];
    const float* bsrc1 = (const float*)d_in[6];
    const float* Wdst1 = (const float*)d_in[7];
    const float* bdst1 = (const float*)d_in[8];
    const float* attn1 = (const float*)d_in[9];
    const float* Wsrc2 = (const float*)d_in[10];
    const float* bsrc2 = (const float*)d_in[11];
    const float* Wdst2 = (const float*)d_in[12];
    const float* bdst2 = (const float*)d_in[13];
    const float* attn2 = (const float*)d_in[14];

    int n_nodes  = in_sizes[0] / DD;
    int n_edges1 = in_sizes[1];
    int n_edges2 = in_sizes[3];
    float* out = (float*)d_out;

    int nblk4 = (n_nodes * 4 + 255) / 256;
    int nblk  = (n_nodes + 255) / 256;
    // 128 edges per 256-thread block (16 edges/warp)
    int eblk1 = (n_edges1 + 127) / 128;
    int eblk2 = (n_edges2 + 127) / 128;

    transform1_k<<<nblk4, 256>>>(emb, Wsrc1, bsrc1, Wdst1, bdst1, n_nodes);
    edge_kernel_h16x2<<<eblk1, 256>>>(src1, dst1, attn1, n_edges1);
    transform2_fused_k<<<nblk4, 256>>>(Wsrc2, bsrc2, Wdst2, bdst2, n_nodes);
    edge_kernel_h16x2<<<eblk2, 256>>>(src2, dst2, attn2, n_edges2);
    finalize2_k<<<nblk, 256>>>(out, n_nodes);
}

// round 14
// speedup vs baseline: 1.2755x; 1.0092x over previous
#include <cuda_runtime.h>
#include <cuda_fp16.h>
#include <cstdint>

#define NN 100000
#define EE 3200000
#define DD 16
#define ACT_SLOPE 0.01f

// Scratch (device globals: allocation-free rule). 256B-aligned.
__device__ __align__(256) float  g_featS[NN * DD];    // fp32: gathered + products
__device__ __align__(256) __half g_featDh[NN * DD];   // fp16: score-only
// Accumulator rows: 64B each = 16 fp16 numerator halves (32B) + fp32 denom @32B + pad.
__device__ __align__(256) __half g_accRow[NN * 32];

// 256-bit global load (sm_100+).
__device__ __forceinline__ void ldg_v8(const float* __restrict__ p, float* f) {
    asm("ld.global.nc.v8.f32 {%0,%1,%2,%3,%4,%5,%6,%7}, [%8];"
        : "=f"(f[0]), "=f"(f[1]), "=f"(f[2]), "=f"(f[3]),
          "=f"(f[4]), "=f"(f[5]), "=f"(f[6]), "=f"(f[7])
        : "l"(p));
}

__device__ __forceinline__ float4 ldg_v4(const float* __restrict__ p) {
    float4 v;
    asm("ld.global.nc.v4.f32 {%0,%1,%2,%3}, [%4];"
        : "=f"(v.x), "=f"(v.y), "=f"(v.z), "=f"(v.w) : "l"(p));
    return v;
}

__device__ __forceinline__ uint2 ldg_u2(const void* __restrict__ p) {
    uint2 v;
    asm("ld.global.nc.v2.u32 {%0,%1}, [%2];" : "=r"(v.x), "=r"(v.y) : "l"(p));
    return v;
}

// Read an accumulator row: 16 halves -> hv[16] floats, plus denom.
__device__ __forceinline__ float read_acc_row(int n, float* hv) {
    const __half* row = g_accRow + (size_t)n * 32;
    uint4 ra = *reinterpret_cast<const uint4*>(row);      // halves 0..7
    uint4 rb = *reinterpret_cast<const uint4*>(row + 8);  // halves 8..15
    const unsigned int u[8] = {ra.x, ra.y, ra.z, ra.w, rb.x, rb.y, rb.z, rb.w};
#pragma unroll
    for (int i = 0; i < 8; i++) {
        float2 f = __half22float2(*reinterpret_cast<const __half2*>(&u[i]));
        hv[2 * i] = f.x;
        hv[2 * i + 1] = f.y;
    }
    return *reinterpret_cast<const float*>(row + 16);     // denom @ byte 32
}

// Shared transform core: thread q of a node writes chunk [4q,4q+4) of featS
// (fp32) and featDh (fp16), zeroes its 16B slice of the accumulator row.
__device__ __forceinline__ void transform_store(
    const float* hv, const float* sWs, const float* sWd,
    const float* sbs, const float* sbd, int n, int q)
{
    int c0 = q * 4;
    float fs[4], fd[4];
#pragma unroll
    for (int j = 0; j < 4; j++) { fs[j] = sbs[c0 + j]; fd[j] = sbd[c0 + j]; }
#pragma unroll
    for (int i = 0; i < DD; i++) {
        float hi = hv[i];
#pragma unroll
        for (int j = 0; j < 4; j++) {
            fs[j] = fmaf(hi, sWs[i * DD + c0 + j], fs[j]);
            fd[j] = fmaf(hi, sWd[i * DD + c0 + j], fd[j]);
        }
    }
    reinterpret_cast<float4*>(g_featS + (size_t)n * DD)[q] =
        make_float4(fs[0], fs[1], fs[2], fs[3]);
    __half2 d0 = __floats2half2_rn(fd[0], fd[1]);
    __half2 d1 = __floats2half2_rn(fd[2], fd[3]);
    uint2 st;
    st.x = *reinterpret_cast<unsigned int*>(&d0);
    st.y = *reinterpret_cast<unsigned int*>(&d1);
    *reinterpret_cast<uint2*>(g_featDh + (size_t)n * DD + q * 4) = st;
    // zero 16B of the 64B accumulator row (4 threads cover it, incl. denom+pad)
    reinterpret_cast<uint4*>(g_accRow + (size_t)n * 32)[q] =
        make_uint4(0u, 0u, 0u, 0u);
}

// ---------------------------------------------------------------------------
// Kernel 1: layer-1 transform from embedding. 4 threads per node.
// ---------------------------------------------------------------------------
__global__ void __launch_bounds__(256) transform1_k(
    const float* __restrict__ h,
    const float* __restrict__ Wsrc, const float* __restrict__ bsrc,
    const float* __restrict__ Wdst, const float* __restrict__ bdst,
    int n_nodes)
{
    __shared__ float sWs[DD * DD], sWd[DD * DD], sbs[DD], sbd[DD];
    int tid = threadIdx.x;
    if (tid < DD * DD) { sWs[tid] = Wsrc[tid]; sWd[tid] = Wdst[tid]; }
    if (tid < DD)      { sbs[tid] = bsrc[tid]; sbd[tid] = bdst[tid]; }
    __syncthreads();

    int g = blockIdx.x * 256 + tid;
    int n = g >> 2, q = g & 3;
    if (n >= n_nodes) return;

    float hv[DD];
    ldg_v8(h + (size_t)n * DD, hv);
    ldg_v8(h + (size_t)n * DD + 8, hv + 8);
    transform_store(hv, sWs, sWd, sbs, sbd, n, q);
}

// ---------------------------------------------------------------------------
// Kernel 2 (fused): layer-1 finalize + layer-2 transform. 4 threads per node.
// ---------------------------------------------------------------------------
__global__ void __launch_bounds__(256) transform2_fused_k(
    const float* __restrict__ Wsrc, const float* __restrict__ bsrc,
    const float* __restrict__ Wdst, const float* __restrict__ bdst,
    int n_nodes)
{
    __shared__ float sWs[DD * DD], sWd[DD * DD], sbs[DD], sbd[DD];
    int tid = threadIdx.x;
    if (tid < DD * DD) { sWs[tid] = Wsrc[tid]; sWd[tid] = Wdst[tid]; }
    if (tid < DD)      { sbs[tid] = bsrc[tid]; sbd[tid] = bdst[tid]; }
    __syncthreads();

    int g = blockIdx.x * 256 + tid;
    int n = g >> 2, q = g & 3;
    if (n >= n_nodes) return;

    float hv[DD];
    float dn = read_acc_row(n, hv);
    float inv = (dn > 0.f) ? (1.0f / dn) : 0.0f;
#pragma unroll
    for (int k = 0; k < DD; k++) {
        float r = hv[k] * inv;
        hv[k] = (r > 0.f) ? r : ACT_SLOPE * r;
    }
    transform_store(hv, sWs, sWd, sbs, sbd, n, q);
}

// ---------------------------------------------------------------------------
// Kernel 3: edge pass, 4 lanes per edge, FOUR edges per thread (32 edges/warp).
// Four independent edge pipelines per thread (MLP=8 outstanding gathers).
// Lane p handles chunk [4p,4p+4) of each of its edges.
// Numerator accumulated in fp16 (lanes 0,2: one red.v4.f16x2 each per edge);
// lane 1: fp32 denom red. 3 red lanes/edge.
// score = 0.6*dot(a,x) + 0.4*dot(a,|x|)  (== dot(a, lrelu(x,0.2)))
// No segment-max (softmax shift invariance; scores ~N(0,1)).
// ---------------------------------------------------------------------------
#define NE 4
__global__ void __launch_bounds__(256) edge_kernel_h16x4(
    const int* __restrict__ src, const int* __restrict__ dst,
    const float* __restrict__ attn, int n_edges)
{
    __shared__ float sa[DD];
    if (threadIdx.x < DD) sa[threadIdx.x] = attn[threadIdx.x];
    __syncthreads();

    int lane = threadIdx.x & 31;
    int p = lane & 3;
    int sub = lane >> 2;
    int warp_global = (blockIdx.x * 256 + threadIdx.x) >> 5;

    float a0 = sa[p * 4 + 0], a1 = sa[p * 4 + 1];
    float a2 = sa[p * 4 + 2], a3 = sa[p * 4 + 3];

    int  e[NE];
    bool valid[NE];
    int  s[NE], t[NE];
#pragma unroll
    for (int i = 0; i < NE; i++) {
        e[i] = warp_global * (8 * NE) + i * 8 + sub;
        valid[i] = (e[i] < n_edges);
        int ec = valid[i] ? e[i] : 0;
        s[i] = __ldg(&src[ec]);
        t[i] = __ldg(&dst[ec]);
    }

    // issue all gathers before consuming any (8 outstanding loads)
    float4 fa[NE];
    uint2  hb[NE];
#pragma unroll
    for (int i = 0; i < NE; i++)
        fa[i] = ldg_v4(g_featS + (size_t)s[i] * DD + p * 4);
#pragma unroll
    for (int i = 0; i < NE; i++)
        hb[i] = ldg_u2(g_featDh + (size_t)t[i] * DD + p * 4);

    float part[NE];
#pragma unroll
    for (int i = 0; i < NE; i++) {
        float2 b01 = __half22float2(*reinterpret_cast<__half2*>(&hb[i].x));
        float2 b23 = __half22float2(*reinterpret_cast<__half2*>(&hb[i].y));
        float x0 = fa[i].x + b01.x, x1 = fa[i].y + b01.y;
        float x2 = fa[i].z + b23.x, x3 = fa[i].w + b23.y;
        float lin = a0 * x0;
        lin = fmaf(a1, x1, lin);
        lin = fmaf(a2, x2, lin);
        lin = fmaf(a3, x3, lin);
        float ab = a0 * fabsf(x0);
        ab = fmaf(a1, fabsf(x1), ab);
        ab = fmaf(a2, fabsf(x2), ab);
        ab = fmaf(a3, fabsf(x3), ab);
        part[i] = fmaf(0.6f, lin, 0.4f * ab);
    }

    // xor-reduce across 4-lane groups, pipelines interleaved
#pragma unroll
    for (int i = 0; i < NE; i++)
        part[i] += __shfl_xor_sync(0xffffffffu, part[i], 1);
#pragma unroll
    for (int i = 0; i < NE; i++)
        part[i] += __shfl_xor_sync(0xffffffffu, part[i], 2);

    float ex[NE];
#pragma unroll
    for (int i = 0; i < NE; i++) ex[i] = __expf(part[i]);

    // pack products, exchange neighbor pairs, issue reds
    unsigned int u0[NE], u1[NE], o0[NE], o1[NE];
#pragma unroll
    for (int i = 0; i < NE; i++) {
        __half2 q0 = __floats2half2_rn(ex[i] * fa[i].x, ex[i] * fa[i].y);
        __half2 q1 = __floats2half2_rn(ex[i] * fa[i].z, ex[i] * fa[i].w);
        u0[i] = *reinterpret_cast<unsigned int*>(&q0);
        u1[i] = *reinterpret_cast<unsigned int*>(&q1);
    }
#pragma unroll
    for (int i = 0; i < NE; i++) {
        o0[i] = __shfl_xor_sync(0xffffffffu, u0[i], 1);
        o1[i] = __shfl_xor_sync(0xffffffffu, u1[i], 1);
    }

#pragma unroll
    for (int i = 0; i < NE; i++) {
        if (valid[i]) {
            char* row = reinterpret_cast<char*>(g_accRow) + (size_t)t[i] * 64;
            if ((p & 1) == 0) {
                asm volatile("red.global.add.noftz.v4.f16x2 [%0], {%1, %2, %3, %4};"
                             :: "l"(row + (p >> 1) * 16),
                                "r"(u0[i]), "r"(u1[i]), "r"(o0[i]), "r"(o1[i])
                             : "memory");
            } else if (p == 1) {
                asm volatile("red.global.add.f32 [%0], %1;"
                             :: "l"(row + 32), "f"(ex[i]) : "memory");
            }
        }
    }
}

// ---------------------------------------------------------------------------
// Kernel 4: layer-2 finalize -> d_out.
// ---------------------------------------------------------------------------
__global__ void __launch_bounds__(256) finalize2_k(float* __restrict__ out, int n_nodes)
{
    int n = blockIdx.x * blockDim.x + threadIdx.x;
    if (n >= n_nodes) return;

    float hv[DD];
    float dn = read_acc_row(n, hv);
    float inv = (dn > 0.f) ? (1.0f / dn) : 0.0f;

    float4* op = reinterpret_cast<float4*>(out + (size_t)n * DD);
#pragma unroll
    for (int q = 0; q < 4; q++) {
        float r0 = hv[4*q + 0] * inv;
        float r1 = hv[4*q + 1] * inv;
        float r2 = hv[4*q + 2] * inv;
        float r3 = hv[4*q + 3] * inv;
        r0 = (r0 > 0.f) ? r0 : ACT_SLOPE * r0;
        r1 = (r1 > 0.f) ? r1 : ACT_SLOPE * r1;
        r2 = (r2 > 0.f) ? r2 : ACT_SLOPE * r2;
        r3 = (r3 > 0.f) ? r3 : ACT_SLOPE * r3;
        op[q] = make_float4(r0, r1, r2, r3);
    }
}

// ---------------------------------------------------------------------------
extern "C" void kernel_launch(void* const* d_in, const int* in_sizes, int n_in,
                              void* d_out, int out_size)
{
    const float* emb   = (const float*)d_in[0];
    const int*   src1  = (const int*)d_in[1];
    const int*   dst1  = (const int*)d_in[2];
    const int*   src2  = (const int*)d_in[3];
    const int*   dst2  = (const int*)d_in[4];
    const float* Wsrc1 = (const float*)d_in[5];
    const float* bsrc1 = (const float*)d_in[6];
    const float* Wdst1 = (const float*)d_in[7];
    const float* bdst1 = (const float*)d_in[8];
    const float* attn1 = (const float*)d_in[9];
    const float* Wsrc2 = (const float*)d_in[10];
    const float* bsrc2 = (const float*)d_in[11];
    const float* Wdst2 = (const float*)d_in[12];
    const float* bdst2 = (const float*)d_in[13];
    const float* attn2 = (const float*)d_in[14];

    int n_nodes  = in_sizes[0] / DD;
    int n_edges1 = in_sizes[1];
    int n_edges2 = in_sizes[3];
    float* out = (float*)d_out;

    int nblk4 = (n_nodes * 4 + 255) / 256;
    int nblk  = (n_nodes + 255) / 256;
    // 256 edges per 256-thread block (32 edges/warp)
    int eblk1 = (n_edges1 + 255) / 256;
    int eblk2 = (n_edges2 + 255) / 256;

    transform1_k<<<nblk4, 256>>>(emb, Wsrc1, bsrc1, Wdst1, bdst1, n_nodes);
    edge_kernel_h16x4<<<eblk1, 256>>>(src1, dst1, attn1, n_edges1);
    transform2_fused_k<<<nblk4, 256>>>(Wsrc2, bsrc2, Wdst2, bdst2, n_nodes);
    edge_kernel_h16x4<<<eblk2, 256>>>(src2, dst2, attn2, n_edges2);
    finalize2_k<<<nblk, 256>>>(out, n_nodes);
}

// round 16
// speedup vs baseline: 1.3534x; 1.0611x over previous
#include <cuda_runtime.h>
#include <cuda_fp16.h>
#include <cstdint>

#define NN 100000
#define EE 3200000
#define DD 16
#define ACT_SLOPE 0.01f

// Scratch (device globals: allocation-free rule). 256B-aligned.
// Both feature tables fp16 (32B rows). Accumulator rows 64B:
// 16 fp16 numerator halves (32B) + fp32 denom @32B + pad.
__device__ __align__(256) __half g_featSh[NN * DD];
__device__ __align__(256) __half g_featDh[NN * DD];
__device__ __align__(256) __half g_accRow[NN * 32];

__device__ __forceinline__ void ldg_v8(const float* __restrict__ p, float* f) {
    asm("ld.global.nc.v8.f32 {%0,%1,%2,%3,%4,%5,%6,%7}, [%8];"
        : "=f"(f[0]), "=f"(f[1]), "=f"(f[2]), "=f"(f[3]),
          "=f"(f[4]), "=f"(f[5]), "=f"(f[6]), "=f"(f[7])
        : "l"(p));
}

__device__ __forceinline__ uint4 ldg_u4(const void* __restrict__ p) {
    uint4 v;
    asm("ld.global.nc.v4.u32 {%0,%1,%2,%3}, [%4];"
        : "=r"(v.x), "=r"(v.y), "=r"(v.z), "=r"(v.w) : "l"(p));
    return v;
}

// Read an accumulator row: 16 halves -> hv[16] floats, plus denom.
__device__ __forceinline__ float read_acc_row(int n, float* hv) {
    const __half* row = g_accRow + (size_t)n * 32;
    uint4 ra = *reinterpret_cast<const uint4*>(row);
    uint4 rb = *reinterpret_cast<const uint4*>(row + 8);
    const unsigned int u[8] = {ra.x, ra.y, ra.z, ra.w, rb.x, rb.y, rb.z, rb.w};
#pragma unroll
    for (int i = 0; i < 8; i++) {
        float2 f = __half22float2(*reinterpret_cast<const __half2*>(&u[i]));
        hv[2 * i] = f.x;
        hv[2 * i + 1] = f.y;
    }
    return *reinterpret_cast<const float*>(row + 16);     // denom @ byte 32
}

// Shared transform core: thread q of a node writes 4 halves of featSh and
// featDh (chunk [4q,4q+4)), zeroes its 16B slice of the accumulator row.
__device__ __forceinline__ void transform_store(
    const float* hv, const float* sWs, const float* sWd,
    const float* sbs, const float* sbd, int n, int q)
{
    int c0 = q * 4;
    float fs[4], fd[4];
#pragma unroll
    for (int j = 0; j < 4; j++) { fs[j] = sbs[c0 + j]; fd[j] = sbd[c0 + j]; }
#pragma unroll
    for (int i = 0; i < DD; i++) {
        float hi = hv[i];
#pragma unroll
        for (int j = 0; j < 4; j++) {
            fs[j] = fmaf(hi, sWs[i * DD + c0 + j], fs[j]);
            fd[j] = fmaf(hi, sWd[i * DD + c0 + j], fd[j]);
        }
    }
    __half2 s0 = __floats2half2_rn(fs[0], fs[1]);
    __half2 s1 = __floats2half2_rn(fs[2], fs[3]);
    __half2 d0 = __floats2half2_rn(fd[0], fd[1]);
    __half2 d1 = __floats2half2_rn(fd[2], fd[3]);
    uint2 ss, sd;
    ss.x = *reinterpret_cast<unsigned int*>(&s0);
    ss.y = *reinterpret_cast<unsigned int*>(&s1);
    sd.x = *reinterpret_cast<unsigned int*>(&d0);
    sd.y = *reinterpret_cast<unsigned int*>(&d1);
    *reinterpret_cast<uint2*>(g_featSh + (size_t)n * DD + q * 4) = ss;
    *reinterpret_cast<uint2*>(g_featDh + (size_t)n * DD + q * 4) = sd;
    reinterpret_cast<uint4*>(g_accRow + (size_t)n * 32)[q] =
        make_uint4(0u, 0u, 0u, 0u);
}

// ---------------------------------------------------------------------------
// Kernel 1: layer-1 transform from embedding. 4 threads per node.
// ---------------------------------------------------------------------------
__global__ void __launch_bounds__(256) transform1_k(
    const float* __restrict__ h,
    const float* __restrict__ Wsrc, const float* __restrict__ bsrc,
    const float* __restrict__ Wdst, const float* __restrict__ bdst,
    int n_nodes)
{
    __shared__ float sWs[DD * DD], sWd[DD * DD], sbs[DD], sbd[DD];
    int tid = threadIdx.x;
    if (tid < DD * DD) { sWs[tid] = Wsrc[tid]; sWd[tid] = Wdst[tid]; }
    if (tid < DD)      { sbs[tid] = bsrc[tid]; sbd[tid] = bdst[tid]; }
    __syncthreads();

    int g = blockIdx.x * 256 + tid;
    int n = g >> 2, q = g & 3;
    if (n >= n_nodes) return;

    float hv[DD];
    ldg_v8(h + (size_t)n * DD, hv);
    ldg_v8(h + (size_t)n * DD + 8, hv + 8);
    transform_store(hv, sWs, sWd, sbs, sbd, n, q);
}

// ---------------------------------------------------------------------------
// Kernel 2 (fused): layer-1 finalize + layer-2 transform. 4 threads per node.
// ---------------------------------------------------------------------------
__global__ void __launch_bounds__(256) transform2_fused_k(
    const float* __restrict__ Wsrc, const float* __restrict__ bsrc,
    const float* __restrict__ Wdst, const float* __restrict__ bdst,
    int n_nodes)
{
    __shared__ float sWs[DD * DD], sWd[DD * DD], sbs[DD], sbd[DD];
    int tid = threadIdx.x;
    if (tid < DD * DD) { sWs[tid] = Wsrc[tid]; sWd[tid] = Wdst[tid]; }
    if (tid < DD)      { sbs[tid] = bsrc[tid]; sbd[tid] = bdst[tid]; }
    __syncthreads();

    int g = blockIdx.x * 256 + tid;
    int n = g >> 2, q = g & 3;
    if (n >= n_nodes) return;

    float hv[DD];
    float dn = read_acc_row(n, hv);
    float inv = (dn > 0.f) ? (1.0f / dn) : 0.0f;
#pragma unroll
    for (int k = 0; k < DD; k++) {
        float r = hv[k] * inv;
        hv[k] = (r > 0.f) ? r : ACT_SLOPE * r;
    }
    transform_store(hv, sWs, sWd, sbs, sbd, n, q);
}

// ---------------------------------------------------------------------------
// Kernel 3: edge pass, TWO lanes per edge (16 edges/warp), 2 edges/thread.
// Lane p (0/1) handles halves [8p, 8p+8) of featS and featD (16B each, fp16).
// Per 16 edges: 1 featS LDG, 1 featD LDG, ONE red.v4.f16x2 (lane 0 -> row+0,
// lane 1 -> row+16), 1 fp32 denom red (lane 0). 4 wavefronts/edge (was 5).
// score = 0.6*dot(a,x) + 0.4*dot(a,|x|)  (== dot(a, lrelu(x,0.2)))
// No segment-max (softmax shift invariance; scores ~N(0,1)).
// ---------------------------------------------------------------------------
__global__ void __launch_bounds__(256) edge_kernel_2lane(
    const int* __restrict__ src, const int* __restrict__ dst,
    const float* __restrict__ attn, int n_edges)
{
    __shared__ float sa[DD];
    if (threadIdx.x < DD) sa[threadIdx.x] = attn[threadIdx.x];
    __syncthreads();

    int lane = threadIdx.x & 31;
    int p = lane & 1;               // half index within edge
    int sub = lane >> 1;            // edge slot within warp (0..15)
    int warp_global = (blockIdx.x * 256 + threadIdx.x) >> 5;

    float a[8];
#pragma unroll
    for (int k = 0; k < 8; k++) a[k] = sa[p * 8 + k];

    int e0 = warp_global * 32 + sub;
    int e1 = e0 + 16;
    bool valid0 = (e0 < n_edges);
    bool valid1 = (e1 < n_edges);
    int ec0 = valid0 ? e0 : 0;
    int ec1 = valid1 ? e1 : 0;

    int s0 = __ldg(&src[ec0]);
    int s1 = __ldg(&src[ec1]);
    int t0 = __ldg(&dst[ec0]);
    int t1 = __ldg(&dst[ec1]);

    // issue all gathers before consuming (4 outstanding 16B loads)
    uint4 ua0 = ldg_u4(g_featSh + (size_t)s0 * DD + p * 8);
    uint4 ua1 = ldg_u4(g_featSh + (size_t)s1 * DD + p * 8);
    uint4 ub0 = ldg_u4(g_featDh + (size_t)t0 * DD + p * 8);
    uint4 ub1 = ldg_u4(g_featDh + (size_t)t1 * DD + p * 8);

    // unpack featS to fp32
    float fa0[8], fa1[8], fb0[8], fb1[8];
    {
        const unsigned int* w;
        w = &ua0.x;
#pragma unroll
        for (int i = 0; i < 4; i++) {
            float2 f = __half22float2(*reinterpret_cast<const __half2*>(&w[i]));
            fa0[2*i] = f.x; fa0[2*i+1] = f.y;
        }
        w = &ua1.x;
#pragma unroll
        for (int i = 0; i < 4; i++) {
            float2 f = __half22float2(*reinterpret_cast<const __half2*>(&w[i]));
            fa1[2*i] = f.x; fa1[2*i+1] = f.y;
        }
        w = &ub0.x;
#pragma unroll
        for (int i = 0; i < 4; i++) {
            float2 f = __half22float2(*reinterpret_cast<const __half2*>(&w[i]));
            fb0[2*i] = f.x; fb0[2*i+1] = f.y;
        }
        w = &ub1.x;
#pragma unroll
        for (int i = 0; i < 4; i++) {
            float2 f = __half22float2(*reinterpret_cast<const __half2*>(&w[i]));
            fb1[2*i] = f.x; fb1[2*i+1] = f.y;
        }
    }

    // score partials (8 terms per lane)
    float lin0 = 0.f, ab0 = 0.f, lin1 = 0.f, ab1 = 0.f;
#pragma unroll
    for (int k = 0; k < 8; k++) {
        float x = fa0[k] + fb0[k];
        lin0 = fmaf(a[k], x, lin0);
        ab0  = fmaf(a[k], fabsf(x), ab0);
        float y = fa1[k] + fb1[k];
        lin1 = fmaf(a[k], y, lin1);
        ab1  = fmaf(a[k], fabsf(y), ab1);
    }
    float part0 = fmaf(0.6f, lin0, 0.4f * ab0);
    float part1 = fmaf(0.6f, lin1, 0.4f * ab1);

    // one xor: partner lane holds the other half
    part0 += __shfl_xor_sync(0xffffffffu, part0, 1);
    part1 += __shfl_xor_sync(0xffffffffu, part1, 1);

    float ex0 = __expf(part0);
    float ex1 = __expf(part1);

    // pack this lane's 8 products as 4x f16x2 and red (one instr covers both halves)
    unsigned int v0[4], v1[4];
#pragma unroll
    for (int i = 0; i < 4; i++) {
        __half2 h0 = __floats2half2_rn(ex0 * fa0[2*i], ex0 * fa0[2*i+1]);
        __half2 h1 = __floats2half2_rn(ex1 * fa1[2*i], ex1 * fa1[2*i+1]);
        v0[i] = *reinterpret_cast<unsigned int*>(&h0);
        v1[i] = *reinterpret_cast<unsigned int*>(&h1);
    }

    if (valid0) {
        char* row = reinterpret_cast<char*>(g_accRow) + (size_t)t0 * 64;
        asm volatile("red.global.add.noftz.v4.f16x2 [%0], {%1, %2, %3, %4};"
                     :: "l"(row + p * 16), "r"(v0[0]), "r"(v0[1]), "r"(v0[2]), "r"(v0[3])
                     : "memory");
        if (p == 0)
            asm volatile("red.global.add.f32 [%0], %1;"
                         :: "l"(row + 32), "f"(ex0) : "memory");
    }
    if (valid1) {
        char* row = reinterpret_cast<char*>(g_accRow) + (size_t)t1 * 64;
        asm volatile("red.global.add.noftz.v4.f16x2 [%0], {%1, %2, %3, %4};"
                     :: "l"(row + p * 16), "r"(v1[0]), "r"(v1[1]), "r"(v1[2]), "r"(v1[3])
                     : "memory");
        if (p == 0)
            asm volatile("red.global.add.f32 [%0], %1;"
                         :: "l"(row + 32), "f"(ex1) : "memory");
    }
}

// ---------------------------------------------------------------------------
// Kernel 4: layer-2 finalize -> d_out.
// ---------------------------------------------------------------------------
__global__ void __launch_bounds__(256) finalize2_k(float* __restrict__ out, int n_nodes)
{
    int n = blockIdx.x * blockDim.x + threadIdx.x;
    if (n >= n_nodes) return;

    float hv[DD];
    float dn = read_acc_row(n, hv);
    float inv = (dn > 0.f) ? (1.0f / dn) : 0.0f;

    float4* op = reinterpret_cast<float4*>(out + (size_t)n * DD);
#pragma unroll
    for (int q = 0; q < 4; q++) {
        float r0 = hv[4*q + 0] * inv;
        float r1 = hv[4*q + 1] * inv;
        float r2 = hv[4*q + 2] * inv;
        float r3 = hv[4*q + 3] * inv;
        r0 = (r0 > 0.f) ? r0 : ACT_SLOPE * r0;
        r1 = (r1 > 0.f) ? r1 : ACT_SLOPE * r1;
        r2 = (r2 > 0.f) ? r2 : ACT_SLOPE * r2;
        r3 = (r3 > 0.f) ? r3 : ACT_SLOPE * r3;
        op[q] = make_float4(r0, r1, r2, r3);
    }
}

// ---------------------------------------------------------------------------
extern "C" void kernel_launch(void* const* d_in, const int* in_sizes, int n_in,
                              void* d_out, int out_size)
{
    const float* emb   = (const float*)d_in[0];
    const int*   src1  = (const int*)d_in[1];
    const int*   dst1  = (const int*)d_in[2];
    const int*   src2  = (const int*)d_in[3];
    const int*   dst2  = (const int*)d_in[4];
    const float* Wsrc1 = (const float*)d_in[5];
    const float* bsrc1 = (const float*)d_in[6];
    const float* Wdst1 = (const float*)d_in[7];
    const float* bdst1 = (const float*)d_in[8];
    const float* attn1 = (const float*)d_in[9];
    const float* Wsrc2 = (const float*)d_in[10];
    const float* bsrc2 = (const float*)d_in[11];
    const float* Wdst2 = (const float*)d_in[12];
    const float* bdst2 = (const float*)d_in[13];
    const float* attn2 = (const float*)d_in[14];

    int n_nodes  = in_sizes[0] / DD;
    int n_edges1 = in_sizes[1];
    int n_edges2 = in_sizes[3];
    float* out = (float*)d_out;

    int nblk4 = (n_nodes * 4 + 255) / 256;
    int nblk  = (n_nodes + 255) / 256;
    // 256 edges per 256-thread block (32 edges/warp: 16 slots x ILP2)
    int eblk1 = (n_edges1 + 255) / 256;
    int eblk2 = (n_edges2 + 255) / 256;

    transform1_k<<<nblk4, 256>>>(emb, Wsrc1, bsrc1, Wdst1, bdst1, n_nodes);
    edge_kernel_2lane<<<eblk1, 256>>>(src1, dst1, attn1, n_edges1);
    transform2_fused_k<<<nblk4, 256>>>(Wsrc2, bsrc2, Wdst2, bdst2, n_nodes);
    edge_kernel_2lane<<<eblk2, 256>>>(src2, dst2, attn2, n_edges2);
    finalize2_k<<<nblk, 256>>>(out, n_nodes);
}